// round 2
// baseline (speedup 1.0000x reference)
#include <cuda_runtime.h>

// Head_3539053052498: B=4, N=4096, H=64, input-dim 1.
// Rank-1 structure collapses attention to a masked scalar softmax:
//   out[b,q,h] = Wv[h] * r[b,q],  r = sum_k p[b,q,k]*X[b,k],
//   scores = c * X[b,q] * X[b,k], c = dot(Wq,Wk)/8, mask: dag[k,q]==0.

#define NN  4096
#define BB  4
#define HH  64
#define SPL 16            // k-dimension splits
#define KC  (NN / SPL)    // 256 keys per chunk
#define BLK 128           // threads per CTA in main kernel (1 q per thread)

__device__ float g_c;             // dot(Wq,Wk) * H^-0.5
__device__ float g_absmax[BB];    // max_k |X[b,k]|
__device__ float g_ps[SPL * BB * NN];  // partial sums of exp
__device__ float g_pw[SPL * BB * NN];  // partial sums of exp * x_k

__device__ __forceinline__ float ex2(float x) {
    float y;
    asm("ex2.approx.ftz.f32 %0, %1;" : "=f"(y) : "f"(x));
    return y;
}

// ---------------------------------------------------------------------------
// Kernel A: blocks 0..3 compute g_absmax[b]; block 4 computes g_c.
// ---------------------------------------------------------------------------
__global__ void setup_kernel(const float* __restrict__ X,
                             const float* __restrict__ Wk,
                             const float* __restrict__ Wq) {
    __shared__ float red[256];
    int b = blockIdx.x;
    int t = threadIdx.x;
    if (b < BB) {
        float m = 0.f;
        for (int k = t; k < NN; k += 256)
            m = fmaxf(m, fabsf(X[b * NN + k]));
        red[t] = m;
        __syncthreads();
        for (int off = 128; off > 0; off >>= 1) {
            if (t < off) red[t] = fmaxf(red[t], red[t + off]);
            __syncthreads();
        }
        if (t == 0) g_absmax[b] = red[0];
    } else {
        float p = (t < HH) ? Wq[t] * Wk[t] : 0.f;
        red[t] = p;
        __syncthreads();
        for (int off = 128; off > 0; off >>= 1) {
            if (t < off) red[t] += red[t + off];
            __syncthreads();
        }
        if (t == 0) g_c = red[0] * 0.125f;  // * H^-0.5, H=64
    }
}

// ---------------------------------------------------------------------------
// Kernel B (main, MUFU-bound): grid (NN/BLK, SPL). Each thread owns one query
// q for all 4 batches; iterates keys in its chunk. dag[k*N+q] is coalesced
// across the q-tile and read exactly once chip-wide (streaming hint).
// ---------------------------------------------------------------------------
__global__ void __launch_bounds__(BLK)
attn_kernel(const float* __restrict__ X, const int* __restrict__ dag) {
    __shared__ float4 s_x[KC];  // s_x[k] = {X[0][k0+k], X[1][..], X[2][..], X[3][..]}

    const int q  = blockIdx.x * BLK + threadIdx.x;
    const int k0 = blockIdx.y * KC;

    // Stage this chunk of X for all 4 batches (broadcast-friendly float4 layout).
    for (int i = threadIdx.x; i < KC * BB; i += BLK) {
        int b = i / KC, k = i % KC;
        ((float*)s_x)[k * 4 + b] = X[b * NN + k0 + k];
    }

    const float LOG2E = 1.4426950408889634f;
    const float c = g_c;
    float a2[BB], nb[BB], sum[BB], wsum[BB];
#pragma unroll
    for (int b = 0; b < BB; b++) {
        float a = c * X[b * NN + q];
        a2[b] = a * LOG2E;
        nb[b] = -fabsf(a) * g_absmax[b] * LOG2E;  // bound => exp arg <= 0
        sum[b] = 0.f;
        wsum[b] = 0.f;
    }
    __syncthreads();

    const int* dp = dag + (size_t)k0 * NN + q;
#pragma unroll 4
    for (int k = 0; k < KC; k++) {
        float4 xv = s_x[k];         // LDS.128, warp-uniform broadcast
        int m = __ldcs(dp);         // dag[k0+k][q], streaming (no reuse)
        dp += NN;
        float e0 = ex2(fmaf(a2[0], xv.x, nb[0]));
        float e1 = ex2(fmaf(a2[1], xv.y, nb[1]));
        float e2 = ex2(fmaf(a2[2], xv.z, nb[2]));
        float e3 = ex2(fmaf(a2[3], xv.w, nb[3]));
        if (m) {  // -> ISETP + predicated FADD/FFMA (no divergence cost)
            sum[0] += e0; wsum[0] = fmaf(e0, xv.x, wsum[0]);
            sum[1] += e1; wsum[1] = fmaf(e1, xv.y, wsum[1]);
            sum[2] += e2; wsum[2] = fmaf(e2, xv.z, wsum[2]);
            sum[3] += e3; wsum[3] = fmaf(e3, xv.w, wsum[3]);
        }
    }

    const int s = blockIdx.y;
#pragma unroll
    for (int b = 0; b < BB; b++) {
        g_ps[(s * BB + b) * NN + q] = sum[b];
        g_pw[(s * BB + b) * NN + q] = wsum[b];
    }
}

// ---------------------------------------------------------------------------
// Kernel C: one warp per (b,q) row. Lanes 0..15 gather sum partials,
// lanes 16..31 gather wsum partials; butterfly-reduce each half; then
// rank-1 broadcast write: out[row, h] = r * Wv[h].
// ---------------------------------------------------------------------------
__global__ void final_kernel(const float* __restrict__ Wv,
                             float* __restrict__ out) {
    int w = (blockIdx.x * blockDim.x + threadIdx.x) >> 5;  // row = b*N + q
    int lane = threadIdx.x & 31;
    if (w >= BB * NN) return;

    float v;
    if (lane < SPL) v = g_ps[lane * BB * NN + w];
    else            v = g_pw[(lane - SPL) * BB * NN + w];
#pragma unroll
    for (int off = 8; off > 0; off >>= 1)
        v += __shfl_xor_sync(0xffffffffu, v, off);  // stays within 16-lane halves

    float ssum = __shfl_sync(0xffffffffu, v, 0);
    float wsum = __shfl_sync(0xffffffffu, v, 16);
    float r = (ssum != 0.f) ? (wsum / ssum) : 0.f;  // fully-masked row -> 0

    out[w * HH + lane]      = r * Wv[lane];
    out[w * HH + 32 + lane] = r * Wv[32 + lane];
}

// ---------------------------------------------------------------------------
extern "C" void kernel_launch(void* const* d_in, const int* in_sizes, int n_in,
                              void* d_out, int out_size) {
    const float* X   = (const float*)d_in[0];
    const int*   dag = (const int*)d_in[1];
    const float* Wk  = (const float*)d_in[2];
    const float* Wq  = (const float*)d_in[3];
    const float* Wv  = (const float*)d_in[4];
    float* out = (float*)d_out;

    setup_kernel<<<BB + 1, 256>>>(X, Wk, Wq);
    attn_kernel<<<dim3(NN / BLK, SPL), BLK>>>(X, dag);
    final_kernel<<<(BB * NN * 32 + 255) / 256, 256>>>(Wv, out);
}

// round 3
// speedup vs baseline: 1.2659x; 1.2659x over previous
#include <cuda_runtime.h>

// Head_3539053052498: B=4, N=4096, H=64, input-dim 1.
// Rank-1 collapse: out[b,q,h] = Wv[h]*r[b,q], r = sum_k p*x_k,
// scores = c*x_q*x_k, c = dot(Wq,Wk)/8, mask: dag[k,q]==0.
// Split-softmax over SPL k-chunks with per-chunk shifts; merge in final kernel.

#define NN  4096
#define BB  4
#define HH  64
#define SPL 32            // k-dimension splits
#define KC  (NN / SPL)    // 128 keys per chunk
#define BLK 256           // threads per CTA in main kernel (1 q per thread)

__device__ float g_sh[SPL * BB * NN];  // per-chunk shift (log2 domain, >=0)
__device__ float g_ps[SPL * BB * NN];  // partial sums of 2^(arg - sh)
__device__ float g_pw[SPL * BB * NN];  // partial sums of 2^(arg - sh) * x_k

__device__ __forceinline__ float ex2(float x) {
    float y;
    asm("ex2.approx.ftz.f32 %0, %1;" : "=f"(y) : "f"(x));
    return y;
}

// ---------------------------------------------------------------------------
// Kernel B (main, MUFU-bound): grid (NN/BLK, SPL). Each thread owns one query
// q for all 4 batches; iterates keys in its chunk. Computes c and the chunk
// abs-max of X locally (no setup kernel, no global dependency).
// ---------------------------------------------------------------------------
__global__ void __launch_bounds__(BLK)
attn_kernel(const float* __restrict__ X, const int* __restrict__ dag,
            const float* __restrict__ Wk, const float* __restrict__ Wq) {
    __shared__ float4 s_x[KC];     // s_x[k] = {X[b][k0+k]}_{b=0..3}
    __shared__ float4 s_rmax[KC];  // reduction scratch
    __shared__ float  s_c;
    __shared__ float4 s_max4;

    const int t  = threadIdx.x;
    const int q  = blockIdx.x * BLK + t;
    const int k0 = blockIdx.y * KC;

    // Warp 0: c = dot(Wq,Wk) * H^-0.5 (H=64 -> /8)
    if (t < 32) {
        float p = Wq[t] * Wk[t] + Wq[t + 32] * Wk[t + 32];
#pragma unroll
        for (int off = 16; off > 0; off >>= 1)
            p += __shfl_xor_sync(0xffffffffu, p, off);
        if (t == 0) s_c = p * 0.125f;
    }

    // Stage chunk of X for all 4 batches (batch-interleaved float4 layout).
#pragma unroll
    for (int i = t; i < KC * BB; i += BLK) {
        int b = i >> 7, k = i & (KC - 1);        // KC = 128
        ((float*)s_x)[k * 4 + b] = X[b * NN + k0 + k];
    }
    __syncthreads();

    // Chunk abs-max per batch (128 float4 -> 1 float4).
    if (t < KC) {
        float4 v = s_x[t];
        s_rmax[t] = make_float4(fabsf(v.x), fabsf(v.y), fabsf(v.z), fabsf(v.w));
    }
    __syncthreads();
    if (t < 32) {
        float4 m = s_rmax[t];
#pragma unroll
        for (int j = 1; j < 4; j++) {
            float4 o = s_rmax[t + j * 32];
            m.x = fmaxf(m.x, o.x); m.y = fmaxf(m.y, o.y);
            m.z = fmaxf(m.z, o.z); m.w = fmaxf(m.w, o.w);
        }
#pragma unroll
        for (int off = 16; off > 0; off >>= 1) {
            m.x = fmaxf(m.x, __shfl_xor_sync(0xffffffffu, m.x, off));
            m.y = fmaxf(m.y, __shfl_xor_sync(0xffffffffu, m.y, off));
            m.z = fmaxf(m.z, __shfl_xor_sync(0xffffffffu, m.z, off));
            m.w = fmaxf(m.w, __shfl_xor_sync(0xffffffffu, m.w, off));
        }
        if (t == 0) s_max4 = m;
    }
    __syncthreads();

    const float LOG2E = 1.4426950408889634f;
    const float c = s_c;
    const float4 cmax = s_max4;
    const float cm[BB] = {cmax.x, cmax.y, cmax.z, cmax.w};

    float a2[BB], nb[BB], sh[BB], sum[BB], wsum[BB];
#pragma unroll
    for (int b = 0; b < BB; b++) {
        float a = c * X[b * NN + q];
        a2[b]   = a * LOG2E;
        sh[b]   = fabsf(a) * cm[b] * LOG2E;  // chunk-local bound (log2 domain)
        nb[b]   = -sh[b];                    // => exp2 arg <= 0, overflow-proof
        sum[b]  = 0.f;
        wsum[b] = 0.f;
    }

    const int* dp = dag + (size_t)k0 * NN + q;
#pragma unroll 8
    for (int k = 0; k < KC; k++) {
        float4 xv = s_x[k];          // LDS.128, warp-uniform broadcast
        int m = __ldcs(dp);          // dag[k0+k][q], streaming, coalesced
        dp += NN;
        float e0 = ex2(fmaf(a2[0], xv.x, nb[0]));
        float e1 = ex2(fmaf(a2[1], xv.y, nb[1]));
        float e2 = ex2(fmaf(a2[2], xv.z, nb[2]));
        float e3 = ex2(fmaf(a2[3], xv.w, nb[3]));
        if (m) {                     // predicated FADD/FFMA, no divergence
            sum[0] += e0; wsum[0] = fmaf(e0, xv.x, wsum[0]);
            sum[1] += e1; wsum[1] = fmaf(e1, xv.y, wsum[1]);
            sum[2] += e2; wsum[2] = fmaf(e2, xv.z, wsum[2]);
            sum[3] += e3; wsum[3] = fmaf(e3, xv.w, wsum[3]);
        }
    }

    const int s = blockIdx.y;
#pragma unroll
    for (int b = 0; b < BB; b++) {
        int idx = (s * BB + b) * NN + q;
        g_sh[idx] = sh[b];
        g_ps[idx] = sum[b];
        g_pw[idx] = wsum[b];
    }
}

// ---------------------------------------------------------------------------
// Kernel C: one thread per (b,q) row. Merge SPL shifted partials
// (split-softmax), then rank-1 broadcast write out[row,h] = r * Wv[h].
// Per-s loads are coalesced across threads (consecutive q).
// ---------------------------------------------------------------------------
__global__ void __launch_bounds__(256)
final_kernel(const float* __restrict__ Wv, float* __restrict__ out) {
    int w = blockIdx.x * blockDim.x + threadIdx.x;  // row = b*NN + q
    if (w >= BB * NN) return;

    // Pass 1: global max shift for this row.
    float M = 0.f;
#pragma unroll
    for (int s = 0; s < SPL; s++)
        M = fmaxf(M, g_sh[s * BB * NN + w]);

    // Pass 2: rescale and accumulate.
    float ssum = 0.f, wsum = 0.f;
#pragma unroll
    for (int s = 0; s < SPL; s++) {
        int idx = s * BB * NN + w;
        float f = ex2(g_sh[idx] - M);       // <= 1
        ssum = fmaf(g_ps[idx], f, ssum);
        wsum = fmaf(g_pw[idx], f, wsum);
    }
    float r = (ssum != 0.f) ? (wsum / ssum) : 0.f;  // fully-masked row -> 0

    const float4* Wv4 = (const float4*)Wv;
    float4* out4 = (float4*)out + (size_t)w * (HH / 4);
#pragma unroll
    for (int h = 0; h < HH / 4; h++) {
        float4 v = __ldg(&Wv4[h]);
        out4[h] = make_float4(r * v.x, r * v.y, r * v.z, r * v.w);
    }
}

// ---------------------------------------------------------------------------
extern "C" void kernel_launch(void* const* d_in, const int* in_sizes, int n_in,
                              void* d_out, int out_size) {
    const float* X   = (const float*)d_in[0];
    const int*   dag = (const int*)d_in[1];
    const float* Wk  = (const float*)d_in[2];
    const float* Wq  = (const float*)d_in[3];
    const float* Wv  = (const float*)d_in[4];
    float* out = (float*)d_out;

    attn_kernel<<<dim3(NN / BLK, SPL), BLK>>>(X, dag, Wk, Wq);
    final_kernel<<<(BB * NN + 255) / 256, 256>>>(Wv, out);
}